// round 16
// baseline (speedup 1.0000x reference)
#include <cuda_runtime.h>
#include <cuda_bf16.h>
#include <cuda_fp16.h>
#include <math.h>
#include <stdint.h>

#define Nn 1024
#define Bb 8
#define Ff 128
#define Oo 128
#define Dd 3
#define Ll 2
#define TO 384   // 3*Oo
#define DB (Dd * Bb)
#define NCAT 896 // 3*128 (support) + 384 (gh) + 128 (t)

typedef __nv_bfloat16 bf16;

// ---------------- scratch (device globals: allocation-free) ----------------
__device__ float g_x[(size_t)Nn * Bb * Ff];
__device__ float g_support[(size_t)DB * Nn * Oo];
__device__ float g_gi[(size_t)DB * Nn * TO];
__device__ float g_gh[(size_t)Nn * Bb * TO];
__device__ float g_t[(size_t)Nn * Bb * Oo];
__device__ __align__(256) half g_adjf[(size_t)DB * Nn * Nn];   // fp16 adj
__device__ __align__(256) half g_supTh[(size_t)DB * Oo * Nn];  // fp16 split
__device__ __align__(256) half g_supTl[(size_t)DB * Oo * Nn];
__device__ __align__(256) bf16 g_aggh[(size_t)DB * Nn * Oo];
__device__ __align__(256) bf16 g_aggl[(size_t)DB * Nn * Oo];
__device__ __align__(256) bf16 g_xh[(size_t)Nn * Bb * Ff];
__device__ __align__(256) bf16 g_xl[(size_t)Nn * Bb * Ff];
__device__ __align__(256) bf16 g_Wih_h[Ll * TO * Oo], g_Wih_l[Ll * TO * Oo];
__device__ __align__(256) bf16 g_Wcat_h[(size_t)Ll * NCAT * Ff];
__device__ __align__(256) bf16 g_Wcat_l[(size_t)Ll * NCAT * Ff];
__device__ float g_cbias[Ll * NCAT];

__device__ __forceinline__ uint32_t smem_u32(const void* p) {
    uint32_t a;
    asm("{ .reg .u64 t; cvta.to.shared.u64 t, %1; cvt.u32.u64 %0, t; }"
        : "=r"(a) : "l"(p));
    return a;
}

#define LDMX4(r, addr)                                                        \
    asm volatile("ldmatrix.sync.aligned.m8n8.x4.shared.b16 {%0,%1,%2,%3}, [%4];" \
                 : "=r"((r)[0]), "=r"((r)[1]), "=r"((r)[2]), "=r"((r)[3])     \
                 : "r"(addr))

#define MMA16816(c, a, b)                                                     \
    asm volatile(                                                             \
        "mma.sync.aligned.m16n8k16.row.col.f32.bf16.bf16.f32 "                \
        "{%0,%1,%2,%3}, {%4,%5,%6,%7}, {%8,%9}, {%0,%1,%2,%3};"               \
        : "+f"((c)[0]), "+f"((c)[1]), "+f"((c)[2]), "+f"((c)[3])              \
        : "r"((a)[0]), "r"((a)[1]), "r"((a)[2]), "r"((a)[3]),                 \
          "r"((b)[0]), "r"((b)[1]))

#define MMAF16(c, a, b)                                                       \
    asm volatile(                                                             \
        "mma.sync.aligned.m16n8k16.row.col.f32.f16.f16.f32 "                  \
        "{%0,%1,%2,%3}, {%4,%5,%6,%7}, {%8,%9}, {%0,%1,%2,%3};"               \
        : "+f"((c)[0]), "+f"((c)[1]), "+f"((c)[2]), "+f"((c)[3])              \
        : "r"((a)[0]), "r"((a)[1]), "r"((a)[2]), "r"((a)[3]),                 \
          "r"((b)[0]), "r"((b)[1]))

__device__ __forceinline__ void cp16(uint32_t saddr, const void* g) {
    asm volatile("cp.async.cg.shared.global [%0], [%1], 16;" ::"r"(saddr),
                 "l"(g));
}
#define CP_COMMIT() asm volatile("cp.async.commit_group;" ::: "memory")

__device__ __forceinline__ void split2(float v, bf16& h, bf16& l) {
    h = __float2bfloat16(v);
    l = __float2bfloat16(v - __bfloat162float(h));
}
__device__ __forceinline__ void split2h(float v, half& h, half& l) {
    h = __float2half_rn(v);
    l = __float2half_rn(v - __half2float(h));
}

// ---------------- prep kernels ---------------------------------------------
__global__ void split_elem(const float* __restrict__ src, bf16* __restrict__ h,
                           bf16* __restrict__ l, int count) {
    int i = blockIdx.x * blockDim.x + threadIdx.x;
    if (i >= count) return;
    split2(src[i], h[i], l[i]);
}

// build concatenated weight [l][c(896)][k(128)] K-major + bias
__global__ void concat_w(const float* __restrict__ W,
                         const float* __restrict__ Whh,
                         const float* __restrict__ Wh,
                         const float* __restrict__ Bc,
                         const float* __restrict__ bhh,
                         const float* __restrict__ Bh) {
    int idx = blockIdx.x * blockDim.x + threadIdx.x;
    if (idx >= Ll * NCAT * Ff) return;
    const int k = idx & 127;
    const int c = (idx >> 7) % NCAT;
    const int l = idx / (NCAT * Ff);
    float v;
    if (c < 384) {
        const int d = c >> 7, o = c & 127;
        v = W[(((size_t)l * Dd + d) * Ff + k) * Oo + o];
    } else if (c < 768) {
        v = Whh[((size_t)l * TO + (c - 384)) * Oo + k];
    } else {
        v = Wh[((size_t)l * Ff + k) * Oo + (c - 768)];
    }
    bf16 h, lo;
    split2(v, h, lo);
    g_Wcat_h[idx] = h;
    g_Wcat_l[idx] = lo;
    if (k == 0) {
        float bv = (c < 384) ? Bc[(l * Dd + (c >> 7)) * Oo + (c & 127)]
                 : (c < 768) ? bhh[l * TO + (c - 384)]
                             : Bh[l * Oo + (c - 768)];
        g_cbias[l * NCAT + c] = bv;
    }
}

// ---------------- adj fp32 -> fp16 (once per call) --------------------------
__global__ void adj_split(const float4* __restrict__ adj) {
    size_t i = (size_t)blockIdx.x * blockDim.x + threadIdx.x;
    if (i >= (size_t)DB * Nn * Nn / 4) return;
    float4 a = adj[i];
    ((half2*)g_adjf)[i * 2 + 0] = __floats2half2_rn(a.x, a.y);
    ((half2*)g_adjf)[i * 2 + 1] = __floats2half2_rn(a.z, a.w);
}

// ------- support [db][n][o] fp32 -> transposed fp16 hi/lo [db][o][n] -------
__global__ void sup_splitT(const float* __restrict__ sup) {
    __shared__ float tile[32][33];
    const int db = blockIdx.z, n0 = blockIdx.x * 32, o0 = blockIdx.y * 32;
    const int tx = threadIdx.x, ty = threadIdx.y;
    const float* s = sup + (size_t)db * Nn * Oo;
#pragma unroll
    for (int r = 0; r < 4; r++)
        tile[ty + r * 8][tx] = s[(size_t)(n0 + ty + r * 8) * Oo + o0 + tx];
    __syncthreads();
    const size_t ob = (size_t)db * Oo * Nn;
#pragma unroll
    for (int r = 0; r < 4; r++) {
        int o = o0 + ty + r * 8;
        half h, l;
        split2h(tile[tx][ty + r * 8], h, l);
        g_supTh[ob + (size_t)o * Nn + n0 + tx] = h;
        g_supTl[ob + (size_t)o * Nn + n0 + tx] = l;
    }
}

#define PITCH 72
#define PITCH2 (PITCH * 2)                  // 144 bytes/row
#define A64_B (64 * PITCH2)                 // 9216
#define B64_B (128 * PITCH2)                // 18432
#define STG64 (2 * A64_B + 2 * B64_B)       // 55296
#define HG64_SMEM (2 * STG64)               // 110592

// ================= unified split-bf16 HMMA GEMM, M=64 tiles, occ 2 =========
// C[M,N] = A[M,K] @ B[N,K]^T  (operands pre-split bf16 hi/lo, K-major)
// D += Ah*Bh + Ah*Bl + Al*Bh  (fp32 accumulate; ~fp32 precision)
// OUT_MODE 0: fp32 C[z*strideCz + row*Ncols + col]
// OUT_MODE 3: combined routing (support scatter | gh | t+relu), bias = cbias
template <int OUT_MODE, bool BIAS, bool RELU>
__global__ __launch_bounds__(256, 2)
void hmma64(const bf16* __restrict__ Ah_, const bf16* __restrict__ Al_,
            size_t strideAz,
            const bf16* __restrict__ Bh_, const bf16* __restrict__ Bl_,
            size_t strideBz,
            const float* __restrict__ bias,
            float* __restrict__ C, size_t strideCz,
            float* __restrict__ C2, float* __restrict__ C3,
            int Ncols, int K) {
    extern __shared__ bf16 smem[];
    const uint32_t sbase = smem_u32(smem);

    const int tid = threadIdx.x, wid = tid >> 5, lane = tid & 31;
    const int n0 = blockIdx.x * 128, m0 = blockIdx.y * 64, z = blockIdx.z;
    const int wm0 = (wid & 1) * 32;
    const int wn0 = (wid >> 1) * 32;

    const bf16* Ah = Ah_ + (size_t)z * strideAz + (size_t)m0 * K;
    const bf16* Al = Al_ + (size_t)z * strideAz + (size_t)m0 * K;
    const bf16* Bh = Bh_ + (size_t)z * strideBz + (size_t)n0 * K;
    const bf16* Bl = Bl_ + (size_t)z * strideBz + (size_t)n0 * K;

    const int sGrp = tid & 7;
    const uint32_t sOffBase = sGrp * 16;

    float acc[2][4][4];
#pragma unroll
    for (int i = 0; i < 2; i++)
#pragma unroll
        for (int j = 0; j < 4; j++)
#pragma unroll
            for (int q = 0; q < 4; q++) acc[i][j][q] = 0.f;

    const uint32_t lrow = lane & 15;
    const uint32_t lcg = (lane >> 4) * 16;
    const int chunks = K >> 6;

    {
        const uint32_t st = sbase;
#pragma unroll
        for (int k = 0; k < 2; k++) {
            const int row = (tid + k * 256) >> 3;
            const uint32_t so = row * PITCH2 + sOffBase;
            const size_t go = (size_t)row * K + sGrp * 8;
            cp16(st + so, Ah + go);
            cp16(st + A64_B + so, Al + go);
        }
#pragma unroll
        for (int k = 0; k < 4; k++) {
            const int row = (tid + k * 256) >> 3;
            const uint32_t so = row * PITCH2 + sOffBase;
            const size_t go = (size_t)row * K + sGrp * 8;
            cp16(st + 2 * A64_B + so, Bh + go);
            cp16(st + 2 * A64_B + B64_B + so, Bl + go);
        }
        CP_COMMIT();
    }

    for (int c = 0; c < chunks; c++) {
        if (c + 1 < chunks) {
            const uint32_t st = sbase + ((c + 1) & 1) * STG64;
            const int koff = (c + 1) * 64;
#pragma unroll
            for (int k = 0; k < 2; k++) {
                const int row = (tid + k * 256) >> 3;
                const uint32_t so = row * PITCH2 + sOffBase;
                const size_t go = (size_t)row * K + koff + sGrp * 8;
                cp16(st + so, Ah + go);
                cp16(st + A64_B + so, Al + go);
            }
#pragma unroll
            for (int k = 0; k < 4; k++) {
                const int row = (tid + k * 256) >> 3;
                const uint32_t so = row * PITCH2 + sOffBase;
                const size_t go = (size_t)row * K + koff + sGrp * 8;
                cp16(st + 2 * A64_B + so, Bh + go);
                cp16(st + 2 * A64_B + B64_B + so, Bl + go);
            }
            CP_COMMIT();
            asm volatile("cp.async.wait_group 1;" ::: "memory");
        } else {
            asm volatile("cp.async.wait_group 0;" ::: "memory");
        }
        __syncthreads();

        const uint32_t sAh = sbase + (c & 1) * STG64;
        const uint32_t sAl = sAh + A64_B;
        const uint32_t sBh = sAh + 2 * A64_B;
        const uint32_t sBl = sBh + B64_B;

#pragma unroll
        for (int ks = 0; ks < 4; ks++) {
            const uint32_t kb = ks * 32 + lcg;
            uint32_t a_h[2][4], a_l[2][4];
#pragma unroll
            for (int i = 0; i < 2; i++) {
                const uint32_t ro = (wm0 + i * 16 + lrow) * PITCH2 + kb;
                LDMX4(a_h[i], sAh + ro);
                LDMX4(a_l[i], sAl + ro);
            }
            uint32_t b_h[4][2], b_l[4][2];
#pragma unroll
            for (int j2 = 0; j2 < 2; j2++) {
                const uint32_t ro = (wn0 + j2 * 16 + lrow) * PITCH2 + kb;
                uint32_t rh[4], rl[4];
                LDMX4(rh, sBh + ro);
                LDMX4(rl, sBl + ro);
                b_h[2 * j2][0] = rh[0]; b_h[2 * j2][1] = rh[2];
                b_h[2 * j2 + 1][0] = rh[1]; b_h[2 * j2 + 1][1] = rh[3];
                b_l[2 * j2][0] = rl[0]; b_l[2 * j2][1] = rl[2];
                b_l[2 * j2 + 1][0] = rl[1]; b_l[2 * j2 + 1][1] = rl[3];
            }
#pragma unroll
            for (int i = 0; i < 2; i++)
#pragma unroll
                for (int j = 0; j < 4; j++) {
                    MMA16816(acc[i][j], a_h[i], b_h[j]);
                    MMA16816(acc[i][j], a_h[i], b_l[j]);
                    MMA16816(acc[i][j], a_l[i], b_h[j]);
                }
        }
        __syncthreads();
    }

    // ----- epilogue -----
    const int g = lane >> 2, t2 = (lane & 3) * 2;
#pragma unroll
    for (int i = 0; i < 2; i++) {
#pragma unroll
        for (int half_ = 0; half_ < 2; half_++) {
            const int rloc = wm0 + i * 16 + half_ * 8 + g;
            const int row = m0 + rloc;
#pragma unroll
            for (int j = 0; j < 4; j++) {
                const int col = n0 + wn0 + j * 8 + t2;
                float v0 = acc[i][j][half_ * 2 + 0];
                float v1 = acc[i][j][half_ * 2 + 1];
                if (BIAS) {
                    v0 += bias[col];
                    v1 += bias[col + 1];
                }
                if (RELU) { v0 = fmaxf(v0, 0.f); v1 = fmaxf(v1, 0.f); }
                if (OUT_MODE == 0) {
                    const size_t o = (size_t)z * strideCz +
                                     (size_t)row * Ncols + col;
                    *(float2*)(C + o) = make_float2(v0, v1);
                } else {  // combined: [0,384) support | [384,768) gh | t
                    if (col < 384) {
                        const int d = col >> 7, o2 = col & 127;
                        const int b = row & 7, n = row >> 3;
                        const size_t o = (((size_t)(d * Bb + b)) * Nn + n) * Oo + o2;
                        *(float2*)(C + o) = make_float2(v0, v1);
                    } else if (col < 768) {
                        const size_t o = (size_t)row * TO + (col - 384);
                        *(float2*)(C2 + o) = make_float2(v0, v1);
                    } else {
                        const size_t o = (size_t)row * Oo + (col - 768);
                        *(float2*)(C3 + o) =
                            make_float2(fmaxf(v0, 0.f), fmaxf(v1, 0.f));
                    }
                }
            }
        }
    }
}

// ================= agg kernel: fp16 A (single) x fp16 B (hi/lo), occ 2 =====
// C[64,128] = adjf[db] @ supT[db]^T over K=1024; 2 products: A*Bh + A*Bl.
// Output bf16 hi/lo split (feeds bf16 gi GEMM).
#define AGG_STG (A64_B + 2 * B64_B)         // 46080
#define AGG_SMEM (2 * AGG_STG)              // 92160

__global__ __launch_bounds__(256, 2)
void agg_f16(const half* __restrict__ adjf,
             bf16* __restrict__ Ch, bf16* __restrict__ Cl) {
    extern __shared__ bf16 smem[];
    const uint32_t sbase = smem_u32(smem);

    const int tid = threadIdx.x, wid = tid >> 5, lane = tid & 31;
    const int mtile = blockIdx.x, db = blockIdx.y;
    const int wm0 = (wid & 1) * 32;
    const int wn0 = (wid >> 1) * 32;

    const half* A = adjf + ((size_t)db * Nn + mtile * 64) * Nn;
    const half* Bh = g_supTh + (size_t)db * Oo * Nn;
    const half* Bl = g_supTl + (size_t)db * Oo * Nn;

    const int sGrp = tid & 7;
    const uint32_t sOffBase = sGrp * 16;

    float acc[2][4][4];
#pragma unroll
    for (int i = 0; i < 2; i++)
#pragma unroll
        for (int j = 0; j < 4; j++)
#pragma unroll
            for (int q = 0; q < 4; q++) acc[i][j][q] = 0.f;

    const uint32_t lrow = lane & 15;
    const uint32_t lcg = (lane >> 4) * 16;
    const int chunks = Nn >> 6;  // 16

    {
        const uint32_t st = sbase;
#pragma unroll
        for (int k = 0; k < 2; k++) {
            const int row = (tid + k * 256) >> 3;
            const uint32_t so = row * PITCH2 + sOffBase;
            cp16(st + so, A + (size_t)row * Nn + sGrp * 8);
        }
#pragma unroll
        for (int k = 0; k < 4; k++) {
            const int row = (tid + k * 256) >> 3;
            const uint32_t so = row * PITCH2 + sOffBase;
            const size_t go = (size_t)row * Nn + sGrp * 8;
            cp16(st + A64_B + so, Bh + go);
            cp16(st + A64_B + B64_B + so, Bl + go);
        }
        CP_COMMIT();
    }

    for (int c = 0; c < chunks; c++) {
        if (c + 1 < chunks) {
            const uint32_t st = sbase + ((c + 1) & 1) * AGG_STG;
            const int koff = (c + 1) * 64;
#pragma unroll
            for (int k = 0; k < 2; k++) {
                const int row = (tid + k * 256) >> 3;
                const uint32_t so = row * PITCH2 + sOffBase;
                cp16(st + so, A + (size_t)row * Nn + koff + sGrp * 8);
            }
#pragma unroll
            for (int k = 0; k < 4; k++) {
                const int row = (tid + k * 256) >> 3;
                const uint32_t so = row * PITCH2 + sOffBase;
                const size_t go = (size_t)row * Nn + koff + sGrp * 8;
                cp16(st + A64_B + so, Bh + go);
                cp16(st + A64_B + B64_B + so, Bl + go);
            }
            CP_COMMIT();
            asm volatile("cp.async.wait_group 1;" ::: "memory");
        } else {
            asm volatile("cp.async.wait_group 0;" ::: "memory");
        }
        __syncthreads();

        const uint32_t sA = sbase + (c & 1) * AGG_STG;
        const uint32_t sBh = sA + A64_B;
        const uint32_t sBl = sBh + B64_B;

#pragma unroll
        for (int ks = 0; ks < 4; ks++) {
            const uint32_t kb = ks * 32 + lcg;
            uint32_t a[2][4];
#pragma unroll
            for (int i = 0; i < 2; i++) {
                const uint32_t ro = (wm0 + i * 16 + lrow) * PITCH2 + kb;
                LDMX4(a[i], sA + ro);
            }
            uint32_t b_h[4][2], b_l[4][2];
#pragma unroll
            for (int j2 = 0; j2 < 2; j2++) {
                const uint32_t ro = (wn0 + j2 * 16 + lrow) * PITCH2 + kb;
                uint32_t rh[4], rl[4];
                LDMX4(rh, sBh + ro);
                LDMX4(rl, sBl + ro);
                b_h[2 * j2][0] = rh[0]; b_h[2 * j2][1] = rh[2];
                b_h[2 * j2 + 1][0] = rh[1]; b_h[2 * j2 + 1][1] = rh[3];
                b_l[2 * j2][0] = rl[0]; b_l[2 * j2][1] = rl[2];
                b_l[2 * j2 + 1][0] = rl[1]; b_l[2 * j2 + 1][1] = rl[3];
            }
#pragma unroll
            for (int i = 0; i < 2; i++)
#pragma unroll
                for (int j = 0; j < 4; j++) {
                    MMAF16(acc[i][j], a[i], b_h[j]);
                    MMAF16(acc[i][j], a[i], b_l[j]);
                }
        }
        __syncthreads();
    }

    // epilogue: bf16 hi/lo split out
    const int g = lane >> 2, t2 = (lane & 3) * 2;
    const size_t rowBase = (size_t)db * Nn + mtile * 64;
#pragma unroll
    for (int i = 0; i < 2; i++) {
#pragma unroll
        for (int half_ = 0; half_ < 2; half_++) {
            const int rloc = wm0 + i * 16 + half_ * 8 + g;
#pragma unroll
            for (int j = 0; j < 4; j++) {
                const int col = wn0 + j * 8 + t2;
                float v0 = acc[i][j][half_ * 2 + 0];
                float v1 = acc[i][j][half_ * 2 + 1];
                bf16 h0, l0, h1, l1;
                split2(v0, h0, l0);
                split2(v1, h1, l1);
                const size_t o = (rowBase + rloc) * Oo + col;
                *(__nv_bfloat162*)(Ch + o) = __nv_bfloat162(h0, h1);
                *(__nv_bfloat162*)(Cl + o) = __nv_bfloat162(l0, l1);
            }
        }
    }
}

// ---------------- fused GRU (sum over d) + relu + highway ------------------
__global__ void gru_highway(const float* __restrict__ x,
                            const float* __restrict__ gi,
                            const float* __restrict__ gh,
                            const float* __restrict__ t,
                            float* __restrict__ xout,
                            bf16* __restrict__ xh, bf16* __restrict__ xl,
                            int writeSplit) {
    const int idx = blockIdx.x * blockDim.x + threadIdx.x;
    const int o = idx & (Oo - 1);
    const int r = idx >> 7;
    const int b = r & (Bb - 1);
    const int n = r >> 3;

    const float xv = x[idx];
    const float tv = t[idx];
    const size_t ghb = (size_t)r * TO;
    const float hr = gh[ghb + o];
    const float hz = gh[ghb + Oo + o];
    const float hn = gh[ghb + 2 * Oo + o];

    float sum = 0.f;
#pragma unroll
    for (int d = 0; d < Dd; d++) {
        const size_t gb = ((size_t)(d * Bb + b) * Nn + n) * TO;
        const float ir = gi[gb + o];
        const float iz = gi[gb + Oo + o];
        const float in_ = gi[gb + 2 * Oo + o];
        const float rg = 1.f / (1.f + expf(-(ir + hr)));
        const float zg = 1.f / (1.f + expf(-(iz + hz)));
        const float ng = tanhf(in_ + rg * hn);
        sum += (1.f - zg) * ng + zg * xv;
    }
    sum = fmaxf(sum, 0.f);
    const float out = sum * tv + xv * (1.f - tv);
    xout[idx] = out;
    if (writeSplit) {
        bf16 h, l;
        split2(out, h, l);
        xh[idx] = h;
        xl[idx] = l;
    }
}

// ---------------- launch ---------------------------------------------------
extern "C" void kernel_launch(void* const* d_in, const int* in_sizes, int n_in,
                              void* d_out, int out_size) {
    const float* inputs = (const float*)d_in[0];
    const float* adj    = (const float*)d_in[1];
    const float* W      = (const float*)d_in[2];
    const float* Bc     = (const float*)d_in[3];
    const float* Wh     = (const float*)d_in[4];
    const float* Bh     = (const float*)d_in[5];
    const float* Wih    = (const float*)d_in[6];
    const float* Whh    = (const float*)d_in[7];
    const float* bih    = (const float*)d_in[8];
    const float* bhh    = (const float*)d_in[9];

    float *p_x, *p_sup, *p_gi, *p_gh, *p_t, *p_cbias;
    half *p_adjf;
    bf16 *p_aggh, *p_aggl, *p_xh, *p_xl;
    bf16 *p_Wih_h, *p_Wih_l, *p_Wcat_h, *p_Wcat_l;
    cudaGetSymbolAddress((void**)&p_x, g_x);
    cudaGetSymbolAddress((void**)&p_sup, g_support);
    cudaGetSymbolAddress((void**)&p_gi, g_gi);
    cudaGetSymbolAddress((void**)&p_gh, g_gh);
    cudaGetSymbolAddress((void**)&p_t, g_t);
    cudaGetSymbolAddress((void**)&p_adjf, g_adjf);
    cudaGetSymbolAddress((void**)&p_aggh, g_aggh);
    cudaGetSymbolAddress((void**)&p_aggl, g_aggl);
    cudaGetSymbolAddress((void**)&p_xh, g_xh);
    cudaGetSymbolAddress((void**)&p_xl, g_xl);
    cudaGetSymbolAddress((void**)&p_Wih_h, g_Wih_h);
    cudaGetSymbolAddress((void**)&p_Wih_l, g_Wih_l);
    cudaGetSymbolAddress((void**)&p_Wcat_h, g_Wcat_h);
    cudaGetSymbolAddress((void**)&p_Wcat_l, g_Wcat_l);
    cudaGetSymbolAddress((void**)&p_cbias, g_cbias);

    cudaFuncSetAttribute(hmma64<0, true, false>,
                         cudaFuncAttributeMaxDynamicSharedMemorySize, HG64_SMEM);
    cudaFuncSetAttribute(hmma64<3, true, false>,
                         cudaFuncAttributeMaxDynamicSharedMemorySize, HG64_SMEM);
    cudaFuncSetAttribute(agg_f16,
                         cudaFuncAttributeMaxDynamicSharedMemorySize, AGG_SMEM);

    // ---- one-time prep ----
    adj_split<<<(int)(((size_t)DB * Nn * Nn / 4 + 255) / 256), 256>>>(
        (const float4*)adj);
    split_elem<<<(Ll * TO * Oo + 255) / 256, 256>>>(Wih, p_Wih_h, p_Wih_l,
                                                    Ll * TO * Oo);
    split_elem<<<(Nn * Bb * Ff + 255) / 256, 256>>>(inputs, p_xh, p_xl,
                                                    Nn * Bb * Ff);
    concat_w<<<(Ll * NCAT * Ff + 255) / 256, 256>>>(W, Whh, Wh, Bc, bhh, Bh);

    for (int l = 0; l < Ll; l++) {
        const float* xin = (l == 0) ? inputs : p_x;
        float* xout = (l == Ll - 1) ? (float*)d_out : p_x;

        // combined: support (scatter) | gh | t(relu) = x @ Wcat + cbias
        hmma64<3, true, false><<<dim3(NCAT / 128, (Nn * Bb) / 64, 1), 256,
                                 HG64_SMEM>>>(
            p_xh, p_xl, 0,
            p_Wcat_h + (size_t)l * NCAT * Ff, p_Wcat_l + (size_t)l * NCAT * Ff,
            0, p_cbias + l * NCAT, p_sup, 0, p_gh, p_t, NCAT, Ff);

        // supT fp16 hi/lo [db][o][n]
        sup_splitT<<<dim3(Nn / 32, Oo / 32, DB), dim3(32, 8)>>>(p_sup);

        // agg[db] = adjf[db] @ supT[db]^T  -> bf16 hi/lo out (2-product fp16)
        agg_f16<<<dim3(Nn / 64, DB), 256, AGG_SMEM>>>(p_adjf, p_aggh, p_aggl);

        // gi = agg @ Wih^T + bih
        hmma64<0, true, false><<<dim3(TO / 128, (DB * Nn) / 64, 1), 256,
                                 HG64_SMEM>>>(
            p_aggh, p_aggl, 0,
            p_Wih_h + (size_t)l * TO * Oo, p_Wih_l + (size_t)l * TO * Oo, 0,
            bih + (size_t)l * TO, p_gi, 0, nullptr, nullptr, TO, Oo);

        // fused GRU + sum_d + relu + highway (+ emit next layer's x splits)
        gru_highway<<<(Nn * Bb * Oo) / 256, 256>>>(
            xin, p_gi, p_gh, p_t, xout, p_xh, p_xl, (l < Ll - 1) ? 1 : 0);
    }
}

// round 17
// speedup vs baseline: 1.2793x; 1.2793x over previous
#include <cuda_runtime.h>
#include <cuda_bf16.h>
#include <math.h>
#include <stdint.h>

#define Nn 1024
#define Bb 8
#define Ff 128
#define Oo 128
#define Dd 3
#define Ll 2
#define TO 384   // 3*Oo
#define DB (Dd * Bb)
#define NCAT 896 // 3*128 (support) + 384 (gh) + 128 (t)

typedef __nv_bfloat16 bf16;

// ---------------- scratch (device globals: allocation-free) ----------------
__device__ float g_x[(size_t)Nn * Bb * Ff];
__device__ float g_support[(size_t)DB * Nn * Oo];
__device__ float g_gi[(size_t)DB * Nn * TO];
__device__ float g_gh[(size_t)Nn * Bb * TO];
__device__ float g_t[(size_t)Nn * Bb * Oo];
__device__ __align__(256) bf16 g_adjh[(size_t)DB * Nn * Nn];
__device__ __align__(256) bf16 g_adjl[(size_t)DB * Nn * Nn];
__device__ __align__(256) bf16 g_supTh[(size_t)DB * Oo * Nn];
__device__ __align__(256) bf16 g_supTl[(size_t)DB * Oo * Nn];
__device__ __align__(256) bf16 g_aggh[(size_t)DB * Nn * Oo];
__device__ __align__(256) bf16 g_aggl[(size_t)DB * Nn * Oo];
__device__ __align__(256) bf16 g_xh[(size_t)Nn * Bb * Ff];
__device__ __align__(256) bf16 g_xl[(size_t)Nn * Bb * Ff];
__device__ __align__(256) bf16 g_Wih_h[Ll * TO * Oo], g_Wih_l[Ll * TO * Oo];
__device__ __align__(256) bf16 g_Wcat_h[(size_t)Ll * NCAT * Ff];
__device__ __align__(256) bf16 g_Wcat_l[(size_t)Ll * NCAT * Ff];
__device__ float g_cbias[Ll * NCAT];

__device__ __forceinline__ uint32_t smem_u32(const void* p) {
    uint32_t a;
    asm("{ .reg .u64 t; cvta.to.shared.u64 t, %1; cvt.u32.u64 %0, t; }"
        : "=r"(a) : "l"(p));
    return a;
}

#define LDMX4(r, addr)                                                        \
    asm volatile("ldmatrix.sync.aligned.m8n8.x4.shared.b16 {%0,%1,%2,%3}, [%4];" \
                 : "=r"((r)[0]), "=r"((r)[1]), "=r"((r)[2]), "=r"((r)[3])     \
                 : "r"(addr))

#define MMA16816(c, a, b)                                                     \
    asm volatile(                                                             \
        "mma.sync.aligned.m16n8k16.row.col.f32.bf16.bf16.f32 "                \
        "{%0,%1,%2,%3}, {%4,%5,%6,%7}, {%8,%9}, {%0,%1,%2,%3};"               \
        : "+f"((c)[0]), "+f"((c)[1]), "+f"((c)[2]), "+f"((c)[3])              \
        : "r"((a)[0]), "r"((a)[1]), "r"((a)[2]), "r"((a)[3]),                 \
          "r"((b)[0]), "r"((b)[1]))

__device__ __forceinline__ void cp16(uint32_t saddr, const void* g) {
    asm volatile("cp.async.cg.shared.global [%0], [%1], 16;" ::"r"(saddr),
                 "l"(g));
}
#define CP_COMMIT() asm volatile("cp.async.commit_group;" ::: "memory")

__device__ __forceinline__ void split2(float v, bf16& h, bf16& l) {
    h = __float2bfloat16(v);
    l = __float2bfloat16(v - __bfloat162float(h));
}

// ---------------- merged small prep ----------------------------------------
// region 0: Wih split (Ll*TO*Oo = 98304)
// region 1: inputs split (Nn*Bb*Ff = 1048576)
// region 2: Wcat build + cbias (Ll*NCAT*Ff = 229376)
#define PREP_W  (Ll * TO * Oo)
#define PREP_X  (Nn * Bb * Ff)
#define PREP_C  (Ll * NCAT * Ff)
#define PREP_TOTAL (PREP_W + PREP_X + PREP_C)

__global__ void prep_misc(const float* __restrict__ Wih,
                          const float* __restrict__ inputs,
                          const float* __restrict__ W,
                          const float* __restrict__ Whh,
                          const float* __restrict__ Wh,
                          const float* __restrict__ Bc,
                          const float* __restrict__ bhh,
                          const float* __restrict__ Bh) {
    int idx = blockIdx.x * blockDim.x + threadIdx.x;
    if (idx < PREP_W) {
        split2(Wih[idx], g_Wih_h[idx], g_Wih_l[idx]);
        return;
    }
    idx -= PREP_W;
    if (idx < PREP_X) {
        split2(inputs[idx], g_xh[idx], g_xl[idx]);
        return;
    }
    idx -= PREP_X;
    if (idx >= PREP_C) return;
    const int k = idx & 127;
    const int c = (idx >> 7) % NCAT;
    const int l = idx / (NCAT * Ff);
    float v;
    if (c < 384) {
        const int d = c >> 7, o = c & 127;
        v = W[(((size_t)l * Dd + d) * Ff + k) * Oo + o];
    } else if (c < 768) {
        v = Whh[((size_t)l * TO + (c - 384)) * Oo + k];
    } else {
        v = Wh[((size_t)l * Ff + k) * Oo + (c - 768)];
    }
    bf16 h, lo;
    split2(v, h, lo);
    g_Wcat_h[idx] = h;
    g_Wcat_l[idx] = lo;
    if (k == 0) {
        float bv = (c < 384) ? Bc[(l * Dd + (c >> 7)) * Oo + (c & 127)]
                 : (c < 768) ? bhh[l * TO + (c - 384)]
                             : Bh[l * Oo + (c - 768)];
        g_cbias[l * NCAT + c] = bv;
    }
}

// ---------------- adj fp32 -> bf16 hi/lo split (once per call) --------------
__global__ void adj_split(const float4* __restrict__ adj) {
    size_t i = (size_t)blockIdx.x * blockDim.x + threadIdx.x;
    if (i >= (size_t)DB * Nn * Nn / 4) return;
    float4 a = adj[i];
    __nv_bfloat162 h01 = __floats2bfloat162_rn(a.x, a.y);
    __nv_bfloat162 h23 = __floats2bfloat162_rn(a.z, a.w);
    __nv_bfloat162 l01 = __floats2bfloat162_rn(a.x - __low2float(h01),
                                               a.y - __high2float(h01));
    __nv_bfloat162 l23 = __floats2bfloat162_rn(a.z - __low2float(h23),
                                               a.w - __high2float(h23));
    ((__nv_bfloat162*)g_adjh)[i * 2 + 0] = h01;
    ((__nv_bfloat162*)g_adjh)[i * 2 + 1] = h23;
    ((__nv_bfloat162*)g_adjl)[i * 2 + 0] = l01;
    ((__nv_bfloat162*)g_adjl)[i * 2 + 1] = l23;
}

// ------- support [db][n][o] fp32 -> transposed bf16 hi/lo [db][o][n] -------
__global__ void sup_splitT(const float* __restrict__ sup) {
    __shared__ float tile[32][33];
    const int db = blockIdx.z, n0 = blockIdx.x * 32, o0 = blockIdx.y * 32;
    const int tx = threadIdx.x, ty = threadIdx.y;
    const float* s = sup + (size_t)db * Nn * Oo;
#pragma unroll
    for (int r = 0; r < 4; r++)
        tile[ty + r * 8][tx] = s[(size_t)(n0 + ty + r * 8) * Oo + o0 + tx];
    __syncthreads();
    const size_t ob = (size_t)db * Oo * Nn;
#pragma unroll
    for (int r = 0; r < 4; r++) {
        int o = o0 + ty + r * 8;
        bf16 h, l;
        split2(tile[tx][ty + r * 8], h, l);
        g_supTh[ob + (size_t)o * Nn + n0 + tx] = h;
        g_supTl[ob + (size_t)o * Nn + n0 + tx] = l;
    }
}

#define PITCH 72
#define PITCH2 (PITCH * 2)                  // 144 bytes/row
#define A64_B (64 * PITCH2)                 // 9216
#define B64_B (128 * PITCH2)                // 18432
#define STG64 (2 * A64_B + 2 * B64_B)       // 55296
#define HG64_SMEM (2 * STG64)               // 110592

// ================= unified split-bf16 HMMA GEMM, M=64 tiles, occ 2 =========
// C[M,N] = A[M,K] @ B[N,K]^T  (operands pre-split bf16 hi/lo, K-major)
// D += Ah*Bh + Ah*Bl + Al*Bh  (fp32 accumulate; ~fp32 precision)
// CTA tile 64x128; 8 warps in 2M x 4N (32x32 each); double-buffered cp.async.
// OUT_MODE 0: fp32 C[z*strideCz + row*Ncols + col]
// OUT_MODE 2: bf16 hi/lo split out (Ch/Cl), Ncols=128
// OUT_MODE 3: combined routing (support scatter | gh | t+relu), bias = cbias
template <int OUT_MODE, bool BIAS, bool RELU>
__global__ __launch_bounds__(256, 2)
void hmma64(const bf16* __restrict__ Ah_, const bf16* __restrict__ Al_,
            size_t strideAz,
            const bf16* __restrict__ Bh_, const bf16* __restrict__ Bl_,
            size_t strideBz,
            const float* __restrict__ bias,
            float* __restrict__ C, size_t strideCz,
            bf16* __restrict__ Ch, bf16* __restrict__ Cl,
            float* __restrict__ C2, float* __restrict__ C3,
            int Ncols, int K) {
    extern __shared__ bf16 smem[];
    const uint32_t sbase = smem_u32(smem);

    const int tid = threadIdx.x, wid = tid >> 5, lane = tid & 31;
    const int n0 = blockIdx.x * 128, m0 = blockIdx.y * 64, z = blockIdx.z;
    const int wm0 = (wid & 1) * 32;   // 0 or 32
    const int wn0 = (wid >> 1) * 32;  // 0..96

    const bf16* Ah = Ah_ + (size_t)z * strideAz + (size_t)m0 * K;
    const bf16* Al = Al_ + (size_t)z * strideAz + (size_t)m0 * K;
    const bf16* Bh = Bh_ + (size_t)z * strideBz + (size_t)n0 * K;
    const bf16* Bl = Bl_ + (size_t)z * strideBz + (size_t)n0 * K;

    const int sGrp = tid & 7;
    const uint32_t sOffBase = sGrp * 16;

    float acc[2][4][4];
#pragma unroll
    for (int i = 0; i < 2; i++)
#pragma unroll
        for (int j = 0; j < 4; j++)
#pragma unroll
            for (int q = 0; q < 4; q++) acc[i][j][q] = 0.f;

    const uint32_t lrow = lane & 15;
    const uint32_t lcg = (lane >> 4) * 16;
    const int chunks = K >> 6;

    // prefetch chunk 0
    {
        const uint32_t st = sbase;
#pragma unroll
        for (int k = 0; k < 2; k++) {  // A: 64 rows
            const int row = (tid + k * 256) >> 3;
            const uint32_t so = row * PITCH2 + sOffBase;
            const size_t go = (size_t)row * K + sGrp * 8;
            cp16(st + so, Ah + go);
            cp16(st + A64_B + so, Al + go);
        }
#pragma unroll
        for (int k = 0; k < 4; k++) {  // B: 128 rows
            const int row = (tid + k * 256) >> 3;
            const uint32_t so = row * PITCH2 + sOffBase;
            const size_t go = (size_t)row * K + sGrp * 8;
            cp16(st + 2 * A64_B + so, Bh + go);
            cp16(st + 2 * A64_B + B64_B + so, Bl + go);
        }
        CP_COMMIT();
    }

    for (int c = 0; c < chunks; c++) {
        if (c + 1 < chunks) {
            const uint32_t st = sbase + ((c + 1) & 1) * STG64;
            const int koff = (c + 1) * 64;
#pragma unroll
            for (int k = 0; k < 2; k++) {
                const int row = (tid + k * 256) >> 3;
                const uint32_t so = row * PITCH2 + sOffBase;
                const size_t go = (size_t)row * K + koff + sGrp * 8;
                cp16(st + so, Ah + go);
                cp16(st + A64_B + so, Al + go);
            }
#pragma unroll
            for (int k = 0; k < 4; k++) {
                const int row = (tid + k * 256) >> 3;
                const uint32_t so = row * PITCH2 + sOffBase;
                const size_t go = (size_t)row * K + koff + sGrp * 8;
                cp16(st + 2 * A64_B + so, Bh + go);
                cp16(st + 2 * A64_B + B64_B + so, Bl + go);
            }
            CP_COMMIT();
            asm volatile("cp.async.wait_group 1;" ::: "memory");
        } else {
            asm volatile("cp.async.wait_group 0;" ::: "memory");
        }
        __syncthreads();

        const uint32_t sAh = sbase + (c & 1) * STG64;
        const uint32_t sAl = sAh + A64_B;
        const uint32_t sBh = sAh + 2 * A64_B;
        const uint32_t sBl = sBh + B64_B;

#pragma unroll
        for (int ks = 0; ks < 4; ks++) {
            const uint32_t kb = ks * 32 + lcg;
            uint32_t a_h[2][4], a_l[2][4];
#pragma unroll
            for (int i = 0; i < 2; i++) {
                const uint32_t ro = (wm0 + i * 16 + lrow) * PITCH2 + kb;
                LDMX4(a_h[i], sAh + ro);
                LDMX4(a_l[i], sAl + ro);
            }
            uint32_t b_h[4][2], b_l[4][2];
#pragma unroll
            for (int j2 = 0; j2 < 2; j2++) {
                const uint32_t ro = (wn0 + j2 * 16 + lrow) * PITCH2 + kb;
                uint32_t rh[4], rl[4];
                LDMX4(rh, sBh + ro);
                LDMX4(rl, sBl + ro);
                b_h[2 * j2][0] = rh[0]; b_h[2 * j2][1] = rh[2];
                b_h[2 * j2 + 1][0] = rh[1]; b_h[2 * j2 + 1][1] = rh[3];
                b_l[2 * j2][0] = rl[0]; b_l[2 * j2][1] = rl[2];
                b_l[2 * j2 + 1][0] = rl[1]; b_l[2 * j2 + 1][1] = rl[3];
            }
#pragma unroll
            for (int i = 0; i < 2; i++)
#pragma unroll
                for (int j = 0; j < 4; j++) {
                    MMA16816(acc[i][j], a_h[i], b_h[j]);
                    MMA16816(acc[i][j], a_h[i], b_l[j]);
                    MMA16816(acc[i][j], a_l[i], b_h[j]);
                }
        }
        __syncthreads();
    }

    // ----- epilogue -----
    const int g = lane >> 2, t2 = (lane & 3) * 2;
#pragma unroll
    for (int i = 0; i < 2; i++) {
#pragma unroll
        for (int half = 0; half < 2; half++) {
            const int rloc = wm0 + i * 16 + half * 8 + g;  // 0..63
            const int row = m0 + rloc;
#pragma unroll
            for (int j = 0; j < 4; j++) {
                const int col = n0 + wn0 + j * 8 + t2;
                float v0 = acc[i][j][half * 2 + 0];
                float v1 = acc[i][j][half * 2 + 1];
                if (BIAS) {
                    v0 += bias[col];
                    v1 += bias[col + 1];
                }
                if (RELU) { v0 = fmaxf(v0, 0.f); v1 = fmaxf(v1, 0.f); }
                if (OUT_MODE == 0) {
                    const size_t o = (size_t)z * strideCz +
                                     (size_t)row * Ncols + col;
                    *(float2*)(C + o) = make_float2(v0, v1);
                } else if (OUT_MODE == 2) {
                    bf16 h0, l0, h1, l1;
                    split2(v0, h0, l0);
                    split2(v1, h1, l1);
                    const size_t o = (size_t)z * strideCz +
                                     (size_t)row * 128 + col;
                    *(__nv_bfloat162*)(Ch + o) = __nv_bfloat162(h0, h1);
                    *(__nv_bfloat162*)(Cl + o) = __nv_bfloat162(l0, l1);
                } else {  // combined: [0,384) support | [384,768) gh | t
                    if (col < 384) {
                        const int d = col >> 7, o2 = col & 127;
                        const int b = row & 7, n = row >> 3;
                        const size_t o = (((size_t)(d * Bb + b)) * Nn + n) * Oo + o2;
                        *(float2*)(C + o) = make_float2(v0, v1);
                    } else if (col < 768) {
                        const size_t o = (size_t)row * TO + (col - 384);
                        *(float2*)(C2 + o) = make_float2(v0, v1);
                    } else {
                        const size_t o = (size_t)row * Oo + (col - 768);
                        *(float2*)(C3 + o) =
                            make_float2(fmaxf(v0, 0.f), fmaxf(v1, 0.f));
                    }
                }
            }
        }
    }
}

// ---------------- fused GRU (sum over d) + relu + highway ------------------
__global__ void gru_highway(const float* __restrict__ x,
                            const float* __restrict__ gi,
                            const float* __restrict__ gh,
                            const float* __restrict__ t,
                            float* __restrict__ xout,
                            bf16* __restrict__ xh, bf16* __restrict__ xl,
                            int writeSplit) {
    const int idx = blockIdx.x * blockDim.x + threadIdx.x;
    const int o = idx & (Oo - 1);
    const int r = idx >> 7;
    const int b = r & (Bb - 1);
    const int n = r >> 3;

    const float xv = x[idx];
    const float tv = t[idx];
    const size_t ghb = (size_t)r * TO;
    const float hr = gh[ghb + o];
    const float hz = gh[ghb + Oo + o];
    const float hn = gh[ghb + 2 * Oo + o];

    float sum = 0.f;
#pragma unroll
    for (int d = 0; d < Dd; d++) {
        const size_t gb = ((size_t)(d * Bb + b) * Nn + n) * TO;
        const float ir = gi[gb + o];
        const float iz = gi[gb + Oo + o];
        const float in_ = gi[gb + 2 * Oo + o];
        const float rg = 1.f / (1.f + expf(-(ir + hr)));
        const float zg = 1.f / (1.f + expf(-(iz + hz)));
        const float ng = tanhf(in_ + rg * hn);
        sum += (1.f - zg) * ng + zg * xv;
    }
    sum = fmaxf(sum, 0.f);
    const float out = sum * tv + xv * (1.f - tv);
    xout[idx] = out;
    if (writeSplit) {
        bf16 h, l;
        split2(out, h, l);
        xh[idx] = h;
        xl[idx] = l;
    }
}

// ---------------- launch ---------------------------------------------------
extern "C" void kernel_launch(void* const* d_in, const int* in_sizes, int n_in,
                              void* d_out, int out_size) {
    const float* inputs = (const float*)d_in[0];
    const float* adj    = (const float*)d_in[1];
    const float* W      = (const float*)d_in[2];
    const float* Bc     = (const float*)d_in[3];
    const float* Wh     = (const float*)d_in[4];
    const float* Bh     = (const float*)d_in[5];
    const float* Wih    = (const float*)d_in[6];
    const float* Whh    = (const float*)d_in[7];
    const float* bih    = (const float*)d_in[8];
    const float* bhh    = (const float*)d_in[9];

    float *p_x, *p_sup, *p_gi, *p_gh, *p_t, *p_cbias;
    bf16 *p_adjh, *p_adjl, *p_supTh, *p_supTl, *p_aggh, *p_aggl, *p_xh, *p_xl;
    bf16 *p_Wih_h, *p_Wih_l, *p_Wcat_h, *p_Wcat_l;
    cudaGetSymbolAddress((void**)&p_x, g_x);
    cudaGetSymbolAddress((void**)&p_sup, g_support);
    cudaGetSymbolAddress((void**)&p_gi, g_gi);
    cudaGetSymbolAddress((void**)&p_gh, g_gh);
    cudaGetSymbolAddress((void**)&p_t, g_t);
    cudaGetSymbolAddress((void**)&p_adjh, g_adjh);
    cudaGetSymbolAddress((void**)&p_adjl, g_adjl);
    cudaGetSymbolAddress((void**)&p_supTh, g_supTh);
    cudaGetSymbolAddress((void**)&p_supTl, g_supTl);
    cudaGetSymbolAddress((void**)&p_aggh, g_aggh);
    cudaGetSymbolAddress((void**)&p_aggl, g_aggl);
    cudaGetSymbolAddress((void**)&p_xh, g_xh);
    cudaGetSymbolAddress((void**)&p_xl, g_xl);
    cudaGetSymbolAddress((void**)&p_Wih_h, g_Wih_h);
    cudaGetSymbolAddress((void**)&p_Wih_l, g_Wih_l);
    cudaGetSymbolAddress((void**)&p_Wcat_h, g_Wcat_h);
    cudaGetSymbolAddress((void**)&p_Wcat_l, g_Wcat_l);
    cudaGetSymbolAddress((void**)&p_cbias, g_cbias);

    cudaFuncSetAttribute(hmma64<0, true, false>,
                         cudaFuncAttributeMaxDynamicSharedMemorySize, HG64_SMEM);
    cudaFuncSetAttribute(hmma64<2, false, false>,
                         cudaFuncAttributeMaxDynamicSharedMemorySize, HG64_SMEM);
    cudaFuncSetAttribute(hmma64<3, true, false>,
                         cudaFuncAttributeMaxDynamicSharedMemorySize, HG64_SMEM);

    // ---- one-time prep ----
    adj_split<<<(int)(((size_t)DB * Nn * Nn / 4 + 255) / 256), 256>>>(
        (const float4*)adj);
    prep_misc<<<(PREP_TOTAL + 255) / 256, 256>>>(Wih, inputs, W, Whh, Wh, Bc,
                                                 bhh, Bh);

    for (int l = 0; l < Ll; l++) {
        const float* xin = (l == 0) ? inputs : p_x;
        float* xout = (l == Ll - 1) ? (float*)d_out : p_x;

        // combined: support (scatter) | gh | t(relu) = x @ Wcat + cbias
        hmma64<3, true, false><<<dim3(NCAT / 128, (Nn * Bb) / 64, 1), 256,
                                 HG64_SMEM>>>(
            p_xh, p_xl, 0,
            p_Wcat_h + (size_t)l * NCAT * Ff, p_Wcat_l + (size_t)l * NCAT * Ff,
            0, p_cbias + l * NCAT, p_sup, 0, nullptr, nullptr, p_gh, p_t,
            NCAT, Ff);

        // supT hi/lo bf16 [db][o][n]
        sup_splitT<<<dim3(Nn / 32, Oo / 32, DB), dim3(32, 8)>>>(p_sup);

        // agg[db] = adj[db] @ supT[db]^T  -> bf16 hi/lo out
        hmma64<2, false, false><<<dim3(1, Nn / 64, DB), 256, HG64_SMEM>>>(
            p_adjh, p_adjl, (size_t)Nn * Nn, p_supTh, p_supTl, (size_t)Oo * Nn,
            nullptr, nullptr, (size_t)Nn * Oo, p_aggh, p_aggl, nullptr,
            nullptr, Oo, Nn);

        // gi = agg @ Wih^T + bih
        hmma64<0, true, false><<<dim3(TO / 128, (DB * Nn) / 64, 1), 256,
                                 HG64_SMEM>>>(
            p_aggh, p_aggl, 0,
            p_Wih_h + (size_t)l * TO * Oo, p_Wih_l + (size_t)l * TO * Oo, 0,
            bih + (size_t)l * TO, p_gi, 0, nullptr, nullptr, nullptr, nullptr,
            TO, Oo);

        // fused GRU + sum_d + relu + highway (+ emit next layer's x splits)
        gru_highway<<<(Nn * Bb * Oo) / 256, 256>>>(
            xin, p_gi, p_gh, p_t, xout, p_xh, p_xl, (l < Ll - 1) ? 1 : 0);
    }
}